// round 2
// baseline (speedup 1.0000x reference)
#include <cuda_runtime.h>

#define TPB 256
#define R 4
#define SROW 260   // smem row stride in floats (260*4 bytes, 16B-aligned rows)

// Scratch for repacked layer-1 weights: gate-units (i,g,o) contiguous,
// rows padded 87 -> 88 so every row is 16B-aligned and float4-loadable.
__device__ __align__(16) float g_w1p[768 * 88];

__global__ void repack_w1(const float* __restrict__ w1i)
{
    int u = blockIdx.x;     // 0..767 : gate-unit (i:0..255, g:256..511, o:512..767)
    int t = threadIdx.x;    // 0..87
    int g = u >> 8;
    int k = u & 255;
    int srow = (g == 0) ? k : ((g == 1) ? 512 + k : 768 + k);  // skip f-gate rows
    g_w1p[u * 88 + t] = (t < 87) ? w1i[srow * 87 + t] : 0.0f;
}

__device__ __forceinline__ float sigmoidf_(float v) { return 1.0f / (1.0f + expf(-v)); }

// One LSTM step with h_prev = c_prev = 0:
//   z = x @ Wih^T + b ; c = sig(i)*tanh(g) ; h = sig(o)*tanh(c) ; out = tanh(h)
// Pass 1: threads over (gate-unit u, row-pair p) -> z staged in sZ[u*R + r].
// Pass 2: threads over (hidden k, row r) -> activations into sOut.
template<int D, int H>
__device__ void lstm_layer(const float* __restrict__ sIn, float* __restrict__ sOut,
                           float* __restrict__ sZ,
                           const float* __restrict__ Wi, const float* __restrict__ Wg,
                           const float* __restrict__ Wo,
                           const float* __restrict__ bi, const float* __restrict__ bg,
                           const float* __restrict__ bo, int t)
{
    for (int m = t; m < 3 * H * (R / 2); m += TPB) {
        int pr = (m & 1) * 2;        // base row of the pair (0 or 2)
        int u  = m >> 1;             // gate-unit 0..3H-1
        int g  = u / H;
        int k  = u - g * H;
        const float* w  = (g == 0 ? Wi : (g == 1 ? Wg : Wo)) + k * D;
        float bv        = (g == 0 ? bi : (g == 1 ? bg : bo))[k];
        float a0 = bv, a1 = bv;
        const float* x0 = sIn + pr * SROW;
        const float* x1 = x0 + SROW;
        #pragma unroll 4
        for (int d = 0; d < D; d += 4) {
            float4 wv = *(const float4*)(w  + d);
            float4 xa = *(const float4*)(x0 + d);
            float4 xb = *(const float4*)(x1 + d);
            a0 += wv.x * xa.x + wv.y * xa.y + wv.z * xa.z + wv.w * xa.w;
            a1 += wv.x * xb.x + wv.y * xb.y + wv.z * xb.z + wv.w * xb.w;
        }
        sZ[u * R + pr]     = a0;
        sZ[u * R + pr + 1] = a1;
    }
    __syncthreads();
    for (int m = t; m < H * R; m += TPB) {
        int r = m & (R - 1);
        int k = m >> 2;
        float zi = sZ[k * R + r];
        float zg = sZ[(H + k) * R + r];
        float zo = sZ[(2 * H + k) * R + r];
        float c  = sigmoidf_(zi) * tanhf(zg);
        float h  = sigmoidf_(zo) * tanhf(c);
        sOut[r * SROW + k] = tanhf(h);
    }
    __syncthreads();
}

template<int D, int H, bool RELU>
__device__ void fc_layer(const float* __restrict__ sIn, float* __restrict__ sOut,
                         const float* __restrict__ W, const float* __restrict__ b, int t)
{
    for (int m = t; m < H * R; m += TPB) {
        int r = m & (R - 1);
        int k = m >> 2;
        const float* w = W + k * D;
        const float* x = sIn + r * SROW;
        float a = b[k];
        #pragma unroll
        for (int d = 0; d < D; d += 4) {
            float4 wv = *(const float4*)(w + d);
            float4 xv = *(const float4*)(x + d);
            a += wv.x * xv.x + wv.y * xv.y + wv.z * xv.z + wv.w * xv.w;
        }
        sOut[r * SROW + k] = RELU ? fmaxf(a, 0.0f) : a;
    }
    __syncthreads();
}

__global__ __launch_bounds__(TPB)
void rnn_fused(const float* __restrict__ x,
               const float* __restrict__ b1,
               const float* __restrict__ w2i, const float* __restrict__ b2,
               const float* __restrict__ w3i, const float* __restrict__ b3,
               const float* __restrict__ w4i, const float* __restrict__ b4,
               const float* __restrict__ f1w, const float* __restrict__ f1b,
               const float* __restrict__ f2w, const float* __restrict__ f2b,
               const float* __restrict__ f3w, const float* __restrict__ f3b,
               const float* __restrict__ f4w, const float* __restrict__ f4b,
               float* __restrict__ out)
{
    __shared__ __align__(16) float sA[R * SROW];
    __shared__ __align__(16) float sB[R * SROW];
    __shared__ float sZ[3 * 256 * R];

    int t = threadIdx.x;
    int row0 = blockIdx.x * R;

    // Load x[t=0] rows row0..row0+3 into sA, zero-pad 87 -> 88.
    for (int i = t; i < R * 88; i += TPB) {
        int r = i / 88, d = i - r * 88;
        sA[r * SROW + d] = (d < 87) ? x[(row0 + r) * 87 + d] : 0.0f;
    }
    __syncthreads();

    // LSTM stack (only i,g,o gates needed; Whh unused since h0=c0=0)
    lstm_layer<88, 256>(sA, sB, sZ, g_w1p, g_w1p + 256 * 88, g_w1p + 512 * 88,
                        b1, b1 + 512, b1 + 768, t);
    lstm_layer<256, 128>(sB, sA, sZ, w2i, w2i + 2 * 128 * 256, w2i + 3 * 128 * 256,
                         b2, b2 + 256, b2 + 384, t);
    lstm_layer<128, 64>(sA, sB, sZ, w3i, w3i + 2 * 64 * 128, w3i + 3 * 64 * 128,
                        b3, b3 + 128, b3 + 192, t);
    lstm_layer<64, 32>(sB, sA, sZ, w4i, w4i + 2 * 32 * 64, w4i + 3 * 32 * 64,
                       b4, b4 + 64, b4 + 96, t);

    // FC head
    fc_layer<32, 128, true >(sA, sB, f1w, f1b, t);
    fc_layer<128, 64, true >(sB, sA, f2w, f2b, t);
    fc_layer<64, 32, true >(sA, sB, f3w, f3b, t);
    fc_layer<32, 3,  false>(sB, sA, f4w, f4b, t);

    if (t < R * 3) {
        int r = t / 3, k = t - r * 3;
        out[(row0 + r) * 3 + k] = sA[r * SROW + k];
    }
}

extern "C" void kernel_launch(void* const* d_in, const int* in_sizes, int n_in,
                              void* d_out, int out_size)
{
    const float* x   = (const float*)d_in[0];
    const float* w1i = (const float*)d_in[1];
    const float* b1  = (const float*)d_in[3];
    const float* w2i = (const float*)d_in[4];
    const float* b2  = (const float*)d_in[6];
    const float* w3i = (const float*)d_in[7];
    const float* b3  = (const float*)d_in[9];
    const float* w4i = (const float*)d_in[10];
    const float* b4  = (const float*)d_in[12];
    const float* f1w = (const float*)d_in[13];
    const float* f1b = (const float*)d_in[14];
    const float* f2w = (const float*)d_in[15];
    const float* f2b = (const float*)d_in[16];
    const float* f3w = (const float*)d_in[17];
    const float* f3b = (const float*)d_in[18];
    const float* f4w = (const float*)d_in[19];
    const float* f4b = (const float*)d_in[20];
    float* out = (float*)d_out;

    repack_w1<<<768, 88>>>(w1i);
    rnn_fused<<<64, TPB>>>(x, b1, w2i, b2, w3i, b3, w4i, b4,
                           f1w, f1b, f2w, f2b, f3w, f3b, f4w, f4b, out);
}

// round 3
// speedup vs baseline: 1.4543x; 1.4543x over previous
#include <cuda_runtime.h>

#define TPB 768
#define R 4
#define SROW 260      // smem activation row stride (floats)
#define SZS 776       // sZ per-row stride (776 % 32 == 8 -> conflict-free pass2)

// Transposed/interleaved weight scratch: for each segment,
// element (d, u) lives at  off + ((d>>2)*C + u)*4 + (d&3)
// so a thread's float4 load of its 4 consecutive d-values is coalesced across u.
#define OFF1 0                       // LSTM1: D=88(pad from 87), C=768
#define OFF2 67584                   // LSTM2: D=256, C=384
#define OFF3 165888                  // LSTM3: D=128, C=192
#define OFF4 190464                  // LSTM4: D=64,  C=96
#define OFF5 196608                  // FC1:   D=32,  C=128
#define OFF6 200704                  // FC2:   D=128, C=64
#define OFF7 208896                  // FC3:   D=64,  C=32
#define OFF8 210944                  // FC4:   D=32,  C=3
#define WTOT 211040

__device__ __align__(16) float g_wt[211072];

__global__ void repack_all(const float* __restrict__ w1i, const float* __restrict__ w2i,
                           const float* __restrict__ w3i, const float* __restrict__ w4i,
                           const float* __restrict__ f1w, const float* __restrict__ f2w,
                           const float* __restrict__ f3w, const float* __restrict__ f4w)
{
    int idx = blockIdx.x * 256 + threadIdx.x;
    if (idx >= WTOT) return;

    const float* src; int off, D, C, H, Dsrc; bool lstm;
    if (idx < OFF2)      { off = OFF1; D = 88;  C = 768; H = 256; Dsrc = 87;  src = w1i; lstm = true; }
    else if (idx < OFF3) { off = OFF2; D = 256; C = 384; H = 128; Dsrc = 256; src = w2i; lstm = true; }
    else if (idx < OFF4) { off = OFF3; D = 128; C = 192; H = 64;  Dsrc = 128; src = w3i; lstm = true; }
    else if (idx < OFF5) { off = OFF4; D = 64;  C = 96;  H = 32;  Dsrc = 64;  src = w4i; lstm = true; }
    else if (idx < OFF6) { off = OFF5; D = 32;  C = 128; H = 0;   Dsrc = 32;  src = f1w; lstm = false; }
    else if (idx < OFF7) { off = OFF6; D = 128; C = 64;  H = 0;   Dsrc = 128; src = f2w; lstm = false; }
    else if (idx < OFF8) { off = OFF7; D = 64;  C = 32;  H = 0;   Dsrc = 64;  src = f3w; lstm = false; }
    else                 { off = OFF8; D = 32;  C = 3;   H = 0;   Dsrc = 32;  src = f4w; lstm = false; }

    int rel = idx - off;
    int lo  = rel & 3;
    int q   = rel >> 2;
    int u   = q % C;
    int d   = (q / C) * 4 + lo;

    float v = 0.0f;
    if (lstm) {
        int g = u / H, k = u - g * H;
        int srow = (g == 0) ? k : ((g == 1) ? 2 * H + k : 3 * H + k);  // gate order i,f,g,o
        if (d < Dsrc) v = src[srow * Dsrc + d];
    } else {
        v = src[u * Dsrc + d];
    }
    g_wt[idx] = v;
}

__device__ __forceinline__ float sigmoidf_(float v) { return 1.0f / (1.0f + expf(-v)); }

// LSTM single step, h0=c0=0: z = x@W^T + b; out = tanh( sig(o)*tanh( sig(i)*tanh(g) ) )
template<int D, int H>
__device__ void lstm_pass(const float* __restrict__ sIn, float* __restrict__ sOut,
                          float* __restrict__ sZ, const float* __restrict__ Wt,
                          const float* __restrict__ b, int t)
{
    constexpr int C  = 3 * H;
    constexpr int G  = TPB / C;            // row groups: 1,2,4,8
    constexpr int RG = (R + G - 1) / G;    // rows per thread: 4,2,1,1
    int u   = t % C;
    int grp = t / C;
    int r0  = grp * RG;

    if (r0 < R) {
        float acc[RG];
        #pragma unroll
        for (int j = 0; j < RG; j++) acc[j] = 0.0f;
        #pragma unroll 4
        for (int d4 = 0; d4 < D / 4; d4++) {
            float4 w = *(const float4*)(Wt + (d4 * C + u) * 4);
            #pragma unroll
            for (int j = 0; j < RG; j++) {
                float4 xv = *(const float4*)(sIn + (r0 + j) * SROW + d4 * 4);
                acc[j] += w.x * xv.x + w.y * xv.y + w.z * xv.z + w.w * xv.w;
            }
        }
        int g = u / H, k = u - g * H;
        float bv = b[((g == 0) ? 0 : (g == 1) ? 2 : 3) * H + k];
        #pragma unroll
        for (int j = 0; j < RG; j++) sZ[(r0 + j) * SZS + u] = acc[j] + bv;
    }
    __syncthreads();

    for (int m = t; m < H * R; m += TPB) {
        int r = m & (R - 1);
        int k = m >> 2;
        float zi = sZ[r * SZS + k];
        float zg = sZ[r * SZS + H + k];
        float zo = sZ[r * SZS + 2 * H + k];
        float c  = sigmoidf_(zi) * tanhf(zg);
        float h  = sigmoidf_(zo) * tanhf(c);
        sOut[r * SROW + k] = tanhf(h);
    }
    __syncthreads();
}

template<int D, int C, bool RELU>
__device__ void fc_pass(const float* __restrict__ sIn, float* __restrict__ sOut,
                        const float* __restrict__ Wt, const float* __restrict__ b, int t)
{
    int u   = t % C;
    int grp = t / C;
    if (grp < R) {
        float acc = 0.0f;
        #pragma unroll
        for (int d4 = 0; d4 < D / 4; d4++) {
            float4 w  = *(const float4*)(Wt + (d4 * C + u) * 4);
            float4 xv = *(const float4*)(sIn + grp * SROW + d4 * 4);
            acc += w.x * xv.x + w.y * xv.y + w.z * xv.z + w.w * xv.w;
        }
        acc += b[u];
        sOut[grp * SROW + u] = RELU ? fmaxf(acc, 0.0f) : acc;
    }
    __syncthreads();
}

__global__ __launch_bounds__(TPB)
void rnn_fused(const float* __restrict__ x,
               const float* __restrict__ b1, const float* __restrict__ b2,
               const float* __restrict__ b3, const float* __restrict__ b4,
               const float* __restrict__ f1b, const float* __restrict__ f2b,
               const float* __restrict__ f3b, const float* __restrict__ f4b,
               float* __restrict__ out)
{
    __shared__ __align__(16) float sA[R * SROW];
    __shared__ __align__(16) float sB[R * SROW];
    __shared__ __align__(16) float sZ[R * SZS];

    int t = threadIdx.x;
    int row0 = blockIdx.x * R;

    // x[t=0] rows row0..row0+3, zero-pad 87 -> 88
    for (int i = t; i < R * 88; i += TPB) {
        int r = i / 88, d = i - r * 88;
        sA[r * SROW + d] = (d < 87) ? x[(row0 + r) * 87 + d] : 0.0f;
    }
    __syncthreads();

    lstm_pass<88, 256>(sA, sB, sZ, g_wt + OFF1, b1, t);
    lstm_pass<256, 128>(sB, sA, sZ, g_wt + OFF2, b2, t);
    lstm_pass<128, 64>(sA, sB, sZ, g_wt + OFF3, b3, t);
    lstm_pass<64, 32>(sB, sA, sZ, g_wt + OFF4, b4, t);

    fc_pass<32, 128, true >(sA, sB, g_wt + OFF5, f1b, t);
    fc_pass<128, 64, true >(sB, sA, g_wt + OFF6, f2b, t);
    fc_pass<64, 32, true >(sA, sB, g_wt + OFF7, f3b, t);
    fc_pass<32, 3,  false>(sB, sA, g_wt + OFF8, f4b, t);

    if (t < R * 3) {
        int r = t / 3, k = t - r * 3;
        out[(row0 + r) * 3 + k] = sA[r * SROW + k];
    }
}

extern "C" void kernel_launch(void* const* d_in, const int* in_sizes, int n_in,
                              void* d_out, int out_size)
{
    const float* x   = (const float*)d_in[0];
    const float* w1i = (const float*)d_in[1];
    const float* b1  = (const float*)d_in[3];
    const float* w2i = (const float*)d_in[4];
    const float* b2  = (const float*)d_in[6];
    const float* w3i = (const float*)d_in[7];
    const float* b3  = (const float*)d_in[9];
    const float* w4i = (const float*)d_in[10];
    const float* b4  = (const float*)d_in[12];
    const float* f1w = (const float*)d_in[13];
    const float* f1b = (const float*)d_in[14];
    const float* f2w = (const float*)d_in[15];
    const float* f2b = (const float*)d_in[16];
    const float* f3w = (const float*)d_in[17];
    const float* f3b = (const float*)d_in[18];
    const float* f4w = (const float*)d_in[19];
    const float* f4b = (const float*)d_in[20];
    float* out = (float*)d_out;

    repack_all<<<(WTOT + 255) / 256, 256>>>(w1i, w2i, w3i, w4i, f1w, f2w, f3w, f4w);
    rnn_fused<<<64, TPB>>>(x, b1, b2, b3, b4, f1b, f2b, f3b, f4b, out);
}